// round 15
// baseline (speedup 1.0000x reference)
#include <cuda_runtime.h>

// ---------------------------------------------------------------------------
// StockLSTM round 13 (re-run; previous attempt hit a container infra failure,
// kernel never executed): k-split packed-f32x2 persistent LSTM, 4 warps/SMSP.
//   Group = 128 threads (4 warps): thread (j, s) = cell j, k-half s, 8 batch.
//   Weights [kk][j*2+s] -> warp LDS.128 contiguous/conflict-free, SAME bytes.
//   h layout [bp][kk][s][2] -> both s-addresses in one 128B line (1 wf).
//   Partial sums reduced with shfl.bfly(1) + add.rn.f32x2; biases pre-halved.
//   Block = 512 thr = 4 groups (32 batch), grid = 128 -> 16 warps/SM.
//   Activations: HW tanh.approx (R12 win, kept).
// ---------------------------------------------------------------------------

#define B_      4096
#define T_      256
#define I_      5
#define H_      64
#define O_      25
#define NBT     8
#define BP      4
#define GROUPS  4
#define GT      128        // threads per group
#define THREADS 512
#define KK      32         // k's per s-half
#define TCH     4
#define XK      6          // x padded width (k = kk + 3s, k=5 zero)

typedef unsigned long long ull;
typedef unsigned int uint;

// ---- prepped weights: float4[kk*128 + j*2 + s] = gates (i,f,g,o), k=kk+32s --
__device__ float4 gW0h[KK * 128];    // layer0 Whh
__device__ float4 gW1x[KK * 128];    // layer1 Wih
__device__ float4 gW1h[KK * 128];    // layer1 Whh
__device__ float4 gW0x[3 * 128];     // layer0 Wih, k = kk + 3s (k=5 -> 0)
__device__ float4 gBias0[H_];        // 0.5*(bih+bhh)  (halved: added by both s)
__device__ float4 gBias1[H_];

__global__ void prep_kernel(const float* __restrict__ Wih0, const float* __restrict__ Whh0,
                            const float* __restrict__ bih0, const float* __restrict__ bhh0,
                            const float* __restrict__ Wih1, const float* __restrict__ Whh1,
                            const float* __restrict__ bih1, const float* __restrict__ bhh1)
{
    const int stride = gridDim.x * blockDim.x;
    const int tid0   = blockIdx.x * blockDim.x + threadIdx.x;

    for (int idx = tid0; idx < KK * 128; idx += stride) {
        const int kk = idx >> 7, lg = idx & 127;
        const int j = lg >> 1, s = lg & 1;
        const int k = kk + 32 * s;
        gW0h[idx] = make_float4(Whh0[j*H_+k],        Whh0[(H_+j)*H_+k],
                                Whh0[(2*H_+j)*H_+k], Whh0[(3*H_+j)*H_+k]);
        gW1x[idx] = make_float4(Wih1[j*H_+k],        Wih1[(H_+j)*H_+k],
                                Wih1[(2*H_+j)*H_+k], Wih1[(3*H_+j)*H_+k]);
        gW1h[idx] = make_float4(Whh1[j*H_+k],        Whh1[(H_+j)*H_+k],
                                Whh1[(2*H_+j)*H_+k], Whh1[(3*H_+j)*H_+k]);
    }
    for (int idx = tid0; idx < 3 * 128; idx += stride) {
        const int kk = idx >> 7, lg = idx & 127;
        const int j = lg >> 1, s = lg & 1;
        const int k = kk + 3 * s;           // 0..5; k=5 is zero pad
        if (k < I_) {
            gW0x[idx] = make_float4(Wih0[j*I_+k],        Wih0[(H_+j)*I_+k],
                                    Wih0[(2*H_+j)*I_+k], Wih0[(3*H_+j)*I_+k]);
        } else {
            gW0x[idx] = make_float4(0.f, 0.f, 0.f, 0.f);
        }
    }
    for (int j = tid0; j < H_; j += stride) {
        gBias0[j] = make_float4(0.5f*(bih0[j]      + bhh0[j]),
                                0.5f*(bih0[H_+j]   + bhh0[H_+j]),
                                0.5f*(bih0[2*H_+j] + bhh0[2*H_+j]),
                                0.5f*(bih0[3*H_+j] + bhh0[3*H_+j]));
        gBias1[j] = make_float4(0.5f*(bih1[j]      + bhh1[j]),
                                0.5f*(bih1[H_+j]   + bhh1[H_+j]),
                                0.5f*(bih1[2*H_+j] + bhh1[2*H_+j]),
                                0.5f*(bih1[3*H_+j] + bhh1[3*H_+j]));
    }
}

// ---- packed helpers -------------------------------------------------------
__device__ __forceinline__ ull dup2(float v) {
    ull r; asm("mov.b64 %0, {%1, %1};" : "=l"(r) : "f"(v)); return r;
}
__device__ __forceinline__ void unpk(float& lo, float& hi, ull v) {
    asm("mov.b64 {%0, %1}, %2;" : "=f"(lo), "=f"(hi) : "l"(v));
}
__device__ __forceinline__ void fma2(ull& d, ull a, ull b) {
    asm("fma.rn.f32x2 %0, %1, %2, %3;" : "=l"(d) : "l"(a), "l"(b), "l"(d));
}
// cross-half reduction: v += v(lane^1)   (both lanes end with the full sum)
__device__ __forceinline__ void redx1(ull& v) {
    uint lo, hi;
    asm("mov.b64 {%0, %1}, %2;" : "=r"(lo), "=r"(hi) : "l"(v));
    lo = __shfl_xor_sync(0xffffffffu, lo, 1);
    hi = __shfl_xor_sync(0xffffffffu, hi, 1);
    ull o; asm("mov.b64 %0, {%1, %2};" : "=l"(o) : "r"(lo), "r"(hi));
    asm("add.rn.f32x2 %0, %1, %2;" : "=l"(v) : "l"(v), "l"(o));
}
__device__ __forceinline__ float tanh_f(float v) {
    float r; asm("tanh.approx.f32 %0, %1;" : "=f"(r) : "f"(v)); return r;
}
__device__ __forceinline__ float sigm(float v) {
    float r; asm("tanh.approx.f32 %0, %1;" : "=f"(r) : "f"(0.5f * v));
    return fmaf(r, 0.5f, 0.5f);
}
__device__ __forceinline__ void barg(int g) {
    asm volatile("bar.sync %0, %1;" :: "r"(1 + g), "r"(GT) : "memory");
}

// SMEM: (4096*3 + 384) f4 weights + (2048 + 2048 + 768) floats = 222208 B
#define SM_BYTES 222208

__global__ __launch_bounds__(THREADS, 1)
void lstm_kernel(const float* __restrict__ x,
                 const float* __restrict__ Wfc, const float* __restrict__ bfc,
                 float* __restrict__ out)
{
    extern __shared__ float4 smem[];
    float4* sW0h = smem;                    // 4096 f4
    float4* sW1x = smem + 4096;             // 4096
    float4* sW1h = smem + 8192;             // 4096
    float4* sW0x = smem + 12288;            // 384
    float*  sf   = reinterpret_cast<float*>(smem + 12672);
    float*  h1T  = sf;                      // [4 grp][BP][32 kk][2 s][2 e] = 2048 f
    float*  h2T  = sf + 2048;               // 2048 f
    float*  sxT  = sf + 4096;               // [4 grp][BP][TCH*6][2 e]     = 768 f

    const int tid = threadIdx.x;

    for (int i = tid; i < KK * 128; i += THREADS) {
        sW0h[i] = gW0h[i]; sW1x[i] = gW1x[i]; sW1h[i] = gW1h[i];
    }
    for (int i = tid; i < 3 * 128; i += THREADS) sW0x[i] = gW0x[i];
    for (int i = tid; i < 4096; i += THREADS) h1T[i] = 0.f;   // h1 + h2
    __syncthreads();

    const int g  = tid >> 7;                // group
    const int lg = tid & 127;               // lane-in-group
    const int j  = lg >> 1;                 // cell
    const int s  = lg & 1;                  // k-half
    const int b0 = blockIdx.x * (GROUPS * NBT) + g * NBT;

    float* h1 = h1T + g * (BP * 128);       // [bp*128 + kk*4 + s*2 + e]
    float* h2 = h2T + g * (BP * 128);
    float* sx = sxT + g * (BP * TCH * XK * 2);   // [bp*48 + (tt*6+k6)*2 + e]

    const float4 bv0 = gBias0[j];
    const float4 bv1 = gBias1[j];
    const ull bi0 = dup2(bv0.x), bf0 = dup2(bv0.y), bg0 = dup2(bv0.z), bo0 = dup2(bv0.w);
    const ull bi1 = dup2(bv1.x), bf1 = dup2(bv1.y), bg1 = dup2(bv1.z), bo1 = dup2(bv1.w);

    // h-store position for this thread's cell j
    const int hp = (j & 31) * 4 + (j >> 5) * 2;
    const int bq0 = 2 * s, bq1 = 2 * s + 1;     // bp-halves this thread stores

    float c1[NBT], c2[NBT];
#pragma unroll
    for (int b = 0; b < NBT; ++b) { c1[b] = 0.f; c2[b] = 0.f; }

    ull ai[BP], af[BP], ag[BP], ao[BP];

#pragma unroll 1
    for (int t = 0; t < T_; ++t) {
        // ---- stage x chunk (group-local), padded to 6 with zero ----
        if ((t & (TCH - 1)) == 0) {
            for (int i = lg; i < NBT * TCH * XK; i += GT) {
                const int bl = i & 7;
                const int r  = i >> 3;          // 0..23 = tt*6 + k6
                const int tt = r / 6, k6 = r - tt * 6;
                const int bp = bl >> 1, e = bl & 1;
                float v = 0.f;
                if (k6 < I_)
                    v = x[(size_t)(b0 + bl) * (T_ * I_) + (t + tt) * I_ + k6];
                sx[bp * (TCH * XK * 2) + r * 2 + e] = v;
            }
            barg(g);
        }

        // ================= layer 0 =================
#pragma unroll
        for (int bp = 0; bp < BP; ++bp) { ai[bp]=bi0; af[bp]=bf0; ag[bp]=bg0; ao[bp]=bo0; }
#pragma unroll 8
        for (int kk = 0; kk < KK; ++kk) {
            const float4 w = sW0h[kk * 128 + lg];
            const ull wi = dup2(w.x), wf = dup2(w.y), wg = dup2(w.z), wo = dup2(w.w);
#pragma unroll
            for (int bp = 0; bp < BP; ++bp) {
                const ull hv = *reinterpret_cast<const ull*>(h1 + bp * 128 + kk * 4 + s * 2);
                fma2(ai[bp], wi, hv); fma2(af[bp], wf, hv);
                fma2(ag[bp], wg, hv); fma2(ao[bp], wo, hv);
            }
        }
#pragma unroll
        for (int kk = 0; kk < 3; ++kk) {
            const float4 w = sW0x[kk * 128 + lg];
            const ull wi = dup2(w.x), wf = dup2(w.y), wg = dup2(w.z), wo = dup2(w.w);
            const int xoff = ((t & (TCH - 1)) * XK + kk + 3 * s) * 2;
#pragma unroll
            for (int bp = 0; bp < BP; ++bp) {
                const ull xv = *reinterpret_cast<const ull*>(sx + bp * (TCH * XK * 2) + xoff);
                fma2(ai[bp], wi, xv); fma2(af[bp], wf, xv);
                fma2(ag[bp], wg, xv); fma2(ao[bp], wo, xv);
            }
        }
        // cross-half reduction (both lanes end with full sums)
#pragma unroll
        for (int bp = 0; bp < BP; ++bp) { redx1(ai[bp]); redx1(af[bp]); redx1(ag[bp]); redx1(ao[bp]); }

        float h1v[NBT];
#pragma unroll
        for (int bp = 0; bp < BP; ++bp) {
            float i0,i1,f0,f1,g0,g1,o0,o1;
            unpk(i0,i1,ai[bp]); unpk(f0,f1,af[bp]); unpk(g0,g1,ag[bp]); unpk(o0,o1,ao[bp]);
            const float cA = sigm(f0)*c1[2*bp]   + sigm(i0)*tanh_f(g0);
            const float cB = sigm(f1)*c1[2*bp+1] + sigm(i1)*tanh_f(g1);
            c1[2*bp]   = cA; h1v[2*bp]   = sigm(o0)*tanh_f(cA);
            c1[2*bp+1] = cB; h1v[2*bp+1] = sigm(o1)*tanh_f(cB);
        }
        barg(g);                               // all reads of h1(t-1) done
        *reinterpret_cast<float2*>(h1 + bq0 * 128 + hp) = make_float2(h1v[2*bq0], h1v[2*bq0+1]);
        *reinterpret_cast<float2*>(h1 + bq1 * 128 + hp) = make_float2(h1v[2*bq1], h1v[2*bq1+1]);
        barg(g);                               // h1(t) visible

        // ================= layer 1 =================
#pragma unroll
        for (int bp = 0; bp < BP; ++bp) { ai[bp]=bi1; af[bp]=bf1; ag[bp]=bg1; ao[bp]=bo1; }
#pragma unroll 4
        for (int kk = 0; kk < KK; ++kk) {
            const float4 wx = sW1x[kk * 128 + lg];
            const float4 wh = sW1h[kk * 128 + lg];
            const ull xi = dup2(wx.x), xf = dup2(wx.y), xg = dup2(wx.z), xo = dup2(wx.w);
            const ull hi = dup2(wh.x), hf = dup2(wh.y), hg = dup2(wh.z), ho = dup2(wh.w);
#pragma unroll
            for (int bp = 0; bp < BP; ++bp) {
                const ull xv = *reinterpret_cast<const ull*>(h1 + bp * 128 + kk * 4 + s * 2);
                const ull hv = *reinterpret_cast<const ull*>(h2 + bp * 128 + kk * 4 + s * 2);
                fma2(ai[bp], xi, xv); fma2(af[bp], xf, xv);
                fma2(ag[bp], xg, xv); fma2(ao[bp], xo, xv);
                fma2(ai[bp], hi, hv); fma2(af[bp], hf, hv);
                fma2(ag[bp], hg, hv); fma2(ao[bp], ho, hv);
            }
        }
#pragma unroll
        for (int bp = 0; bp < BP; ++bp) { redx1(ai[bp]); redx1(af[bp]); redx1(ag[bp]); redx1(ao[bp]); }

        float h2v[NBT];
#pragma unroll
        for (int bp = 0; bp < BP; ++bp) {
            float i0,i1,f0,f1,g0,g1,o0,o1;
            unpk(i0,i1,ai[bp]); unpk(f0,f1,af[bp]); unpk(g0,g1,ag[bp]); unpk(o0,o1,ao[bp]);
            const float cA = sigm(f0)*c2[2*bp]   + sigm(i0)*tanh_f(g0);
            const float cB = sigm(f1)*c2[2*bp+1] + sigm(i1)*tanh_f(g1);
            c2[2*bp]   = cA; h2v[2*bp]   = sigm(o0)*tanh_f(cA);
            c2[2*bp+1] = cB; h2v[2*bp+1] = sigm(o1)*tanh_f(cB);
        }
        barg(g);                               // all reads of h2(t-1) done
        *reinterpret_cast<float2*>(h2 + bq0 * 128 + hp) = make_float2(h2v[2*bq0], h2v[2*bq0+1]);
        *reinterpret_cast<float2*>(h2 + bq1 * 128 + hp) = make_float2(h2v[2*bq1], h2v[2*bq1+1]);
        barg(g);                               // h2(t) visible
    }

    // ---- FC on h2(T-1): out[b][o] = sum_k h2[k][b] * Wfc[o][k] + bfc[o] ----
    for (int i = lg; i < NBT * O_; i += GT) {
        const int bl = i / O_;
        const int o  = i - bl * O_;
        const int bp = bl >> 1, e = bl & 1;
        const float* wrow = Wfc + o * H_;
        float acc = bfc[o];
#pragma unroll 8
        for (int k = 0; k < H_; ++k)
            acc += h2[bp * 128 + (k & 31) * 4 + (k >> 5) * 2 + e] * wrow[k];
        out[(size_t)(b0 + bl) * O_ + o] = acc;
    }
}

// ---------------------------------------------------------------------------
extern "C" void kernel_launch(void* const* d_in, const int* in_sizes, int n_in,
                              void* d_out, int out_size)
{
    (void)in_sizes; (void)n_in; (void)out_size;
    const float* x    = (const float*)d_in[0];
    const float* Wih0 = (const float*)d_in[1];
    const float* Whh0 = (const float*)d_in[2];
    const float* bih0 = (const float*)d_in[3];
    const float* bhh0 = (const float*)d_in[4];
    const float* Wih1 = (const float*)d_in[5];
    const float* Whh1 = (const float*)d_in[6];
    const float* bih1 = (const float*)d_in[7];
    const float* bhh1 = (const float*)d_in[8];
    const float* Wfc  = (const float*)d_in[9];
    const float* bfc  = (const float*)d_in[10];
    float* out = (float*)d_out;

    cudaFuncSetAttribute(lstm_kernel, cudaFuncAttributeMaxDynamicSharedMemorySize,
                         SM_BYTES);

    prep_kernel<<<32, 256>>>(Wih0, Whh0, bih0, bhh0, Wih1, Whh1, bih1, bhh1);
    lstm_kernel<<<B_ / (GROUPS * NBT), THREADS, SM_BYTES>>>(x, Wfc, bfc, out);
}

// round 16
// speedup vs baseline: 1.0258x; 1.0258x over previous
#include <cuda_runtime.h>

// ---------------------------------------------------------------------------
// StockLSTM round 16 = R12 champion structure (2198.7us) with MINIMAL barriers:
//   - h1 double-buffered  -> h1 store needs no pre-barrier (WAR gone).
//   - end-of-step barrier deleted (layer0 never reads h2; h2 visibility for
//     layer1(t+1) is covered by bargA(t+1)).
//   - sx double-buffered, prefetched one 4-step chunk ahead -> staging
//     barrier deleted.
//   Step = layer0 -> store h1w -> [x prefetch] -> bargA -> layer1 -> bargB
//          -> store h2.        (2 barriers/step vs 4.25)
// Block = 256 thr = 4 groups of 64; group = 64 cells x 8 batch (4 f32x2
// pairs).  Weights float4[k][j]=(wi,wf,wg,wo) in SMEM.  tanh.approx acts.
// ---------------------------------------------------------------------------

#define B_      4096
#define T_      256
#define I_      5
#define H_      64
#define O_      25
#define NBT     8
#define BP      4
#define GROUPS  4
#define THREADS 256
#define TCH     4

typedef unsigned long long ull;

__device__ float4 gW0h[H_ * H_];
__device__ float4 gW1x[H_ * H_];
__device__ float4 gW1h[H_ * H_];
__device__ float4 gW0x[I_ * H_];
__device__ float4 gBias0[H_];
__device__ float4 gBias1[H_];

__global__ void prep_kernel(const float* __restrict__ Wih0, const float* __restrict__ Whh0,
                            const float* __restrict__ bih0, const float* __restrict__ bhh0,
                            const float* __restrict__ Wih1, const float* __restrict__ Whh1,
                            const float* __restrict__ bih1, const float* __restrict__ bhh1)
{
    const int stride = gridDim.x * blockDim.x;
    const int tid0   = blockIdx.x * blockDim.x + threadIdx.x;

    for (int idx = tid0; idx < H_ * H_; idx += stride) {
        const int k = idx >> 6, j = idx & 63;
        gW0h[idx] = make_float4(Whh0[j*H_+k],        Whh0[(H_+j)*H_+k],
                                Whh0[(2*H_+j)*H_+k], Whh0[(3*H_+j)*H_+k]);
        gW1x[idx] = make_float4(Wih1[j*H_+k],        Wih1[(H_+j)*H_+k],
                                Wih1[(2*H_+j)*H_+k], Wih1[(3*H_+j)*H_+k]);
        gW1h[idx] = make_float4(Whh1[j*H_+k],        Whh1[(H_+j)*H_+k],
                                Whh1[(2*H_+j)*H_+k], Whh1[(3*H_+j)*H_+k]);
    }
    for (int idx = tid0; idx < I_ * H_; idx += stride) {
        const int k = idx >> 6, j = idx & 63;
        gW0x[idx] = make_float4(Wih0[j*I_+k],        Wih0[(H_+j)*I_+k],
                                Wih0[(2*H_+j)*I_+k], Wih0[(3*H_+j)*I_+k]);
    }
    for (int j = tid0; j < H_; j += stride) {
        gBias0[j] = make_float4(bih0[j]      + bhh0[j],
                                bih0[H_+j]   + bhh0[H_+j],
                                bih0[2*H_+j] + bhh0[2*H_+j],
                                bih0[3*H_+j] + bhh0[3*H_+j]);
        gBias1[j] = make_float4(bih1[j]      + bhh1[j],
                                bih1[H_+j]   + bhh1[H_+j],
                                bih1[2*H_+j] + bhh1[2*H_+j],
                                bih1[3*H_+j] + bhh1[3*H_+j]);
    }
}

__device__ __forceinline__ ull dup2(float v) {
    ull r; asm("mov.b64 %0, {%1, %1};" : "=l"(r) : "f"(v)); return r;
}
__device__ __forceinline__ void unpk(float& lo, float& hi, ull v) {
    asm("mov.b64 {%0, %1}, %2;" : "=f"(lo), "=f"(hi) : "l"(v));
}
__device__ __forceinline__ void fma2(ull& d, ull a, ull b) {
    asm("fma.rn.f32x2 %0, %1, %2, %3;" : "=l"(d) : "l"(a), "l"(b), "l"(d));
}
__device__ __forceinline__ float tanh_f(float v) {
    float r; asm("tanh.approx.f32 %0, %1;" : "=f"(r) : "f"(v)); return r;
}
__device__ __forceinline__ float sigm(float v) {
    float r; asm("tanh.approx.f32 %0, %1;" : "=f"(r) : "f"(0.5f * v));
    return fmaf(r, 0.5f, 0.5f);
}
__device__ __forceinline__ void barg(int g) {
    asm volatile("bar.sync %0, 64;" :: "r"(1 + g) : "memory");
}

// SMEM: 201728 B weights + (4096 + 2048 + 1280)*4 = 231424 B  (1 blk/SM; ran R1/R2)
#define SM_BYTES 231424
#define SX_GRP   (BP * TCH * I_ * 2)          // 160 floats per group per buf
#define SX_BUF   (GROUPS * SX_GRP)            // 640 floats per buf

__global__ __launch_bounds__(THREADS)
void lstm_kernel(const float* __restrict__ x,
                 const float* __restrict__ Wfc, const float* __restrict__ bfc,
                 float* __restrict__ out)
{
    extern __shared__ float4 smem[];
    float4* sW0h = smem;                    // 4096 float4
    float4* sW1x = smem + 4096;             // 4096
    float4* sW1h = smem + 8192;             // 4096
    float4* sW0x = smem + 12288;            // 320
    float*  sf   = reinterpret_cast<float*>(smem + 12608);
    float*  h1T  = sf;                      // [2 buf][4 grp][BP][64][2] = 4096 f
    float*  h2T  = sf + 4096;               // [4 grp][BP][64][2]        = 2048 f
    float*  sxT  = sf + 6144;               // [2 buf][4 grp][BP][20][2] = 1280 f

    const int tid = threadIdx.x;

    for (int i = tid; i < H_ * H_; i += THREADS) {
        sW0h[i] = gW0h[i]; sW1x[i] = gW1x[i]; sW1h[i] = gW1h[i];
    }
    for (int i = tid; i < I_ * H_; i += THREADS) sW0x[i] = gW0x[i];
    for (int i = tid; i < 6144; i += THREADS) h1T[i] = 0.f;   // h1 bufs + h2

    const int g  = tid >> 6;
    const int j  = tid & 63;
    const int b0 = blockIdx.x * (GROUPS * NBT) + g * NBT;

    float* h1g = h1T + g * (BP * H_ * 2);   // + buf*2048
    float* h2  = h2T + g * (BP * H_ * 2);
    float* sxg = sxT + g * SX_GRP;          // + buf*SX_BUF

    // stage x chunk 0 into buf 0
    for (int i = j; i < NBT * TCH * I_; i += 64) {
        const int bl = i & 7;
        const int r  = i >> 3;              // tt*5+kk
        const int bp = bl >> 1, e = bl & 1;
        sxg[bp * (TCH * I_ * 2) + r * 2 + e]
            = x[(size_t)(b0 + bl) * (T_ * I_) + r];
    }
    __syncthreads();

    const float4 bv0 = gBias0[j];
    const float4 bv1 = gBias1[j];
    const ull bi0 = dup2(bv0.x), bf0 = dup2(bv0.y), bg0 = dup2(bv0.z), bo0 = dup2(bv0.w);
    const ull bi1 = dup2(bv1.x), bf1 = dup2(bv1.y), bg1 = dup2(bv1.z), bo1 = dup2(bv1.w);

    float c1[NBT], c2[NBT];
#pragma unroll
    for (int b = 0; b < NBT; ++b) { c1[b] = 0.f; c2[b] = 0.f; }

    ull ai[BP], af[BP], ag[BP], ao[BP];

#pragma unroll 1
    for (int t = 0; t < T_; ++t) {
        const float* h1r = h1g + (t & 1) * 2048;        // h1(t-1)
        float*       h1w = h1g + ((t + 1) & 1) * 2048;  // h1(t)
        const float* sxc = sxg + ((t >> 2) & 1) * SX_BUF;   // current chunk

        // ================= layer 0 =================
#pragma unroll
        for (int bp = 0; bp < BP; ++bp) { ai[bp]=bi0; af[bp]=bf0; ag[bp]=bg0; ao[bp]=bo0; }
#pragma unroll 8
        for (int k = 0; k < H_; ++k) {
            const float4 w = sW0h[k * H_ + j];
            const ull wi = dup2(w.x), wf = dup2(w.y), wg = dup2(w.z), wo = dup2(w.w);
#pragma unroll
            for (int bp = 0; bp < BP; ++bp) {
                const ull hv = *reinterpret_cast<const ull*>(h1r + bp * 128 + k * 2);
                fma2(ai[bp], wi, hv); fma2(af[bp], wf, hv);
                fma2(ag[bp], wg, hv); fma2(ao[bp], wo, hv);
            }
        }
#pragma unroll
        for (int k = 0; k < I_; ++k) {
            const float4 w = sW0x[k * H_ + j];
            const ull wi = dup2(w.x), wf = dup2(w.y), wg = dup2(w.z), wo = dup2(w.w);
            const int xoff = ((t & (TCH - 1)) * I_ + k) * 2;
#pragma unroll
            for (int bp = 0; bp < BP; ++bp) {
                const ull xv = *reinterpret_cast<const ull*>(sxc + bp * (TCH * I_ * 2) + xoff);
                fma2(ai[bp], wi, xv); fma2(af[bp], wf, xv);
                fma2(ag[bp], wg, xv); fma2(ao[bp], wo, xv);
            }
        }
        // layer0 epilogue -> store h1(t) directly (double buffer: no WAR)
#pragma unroll
        for (int bp = 0; bp < BP; ++bp) {
            float i0,i1,f0,f1,g0,g1,o0,o1;
            unpk(i0,i1,ai[bp]); unpk(f0,f1,af[bp]); unpk(g0,g1,ag[bp]); unpk(o0,o1,ao[bp]);
            const float cA = sigm(f0)*c1[2*bp]   + sigm(i0)*tanh_f(g0);
            const float cB = sigm(f1)*c1[2*bp+1] + sigm(i1)*tanh_f(g1);
            c1[2*bp]   = cA;
            c1[2*bp+1] = cB;
            *reinterpret_cast<float2*>(h1w + bp * 128 + j * 2)
                = make_float2(sigm(o0)*tanh_f(cA), sigm(o1)*tanh_f(cB));
        }

        // ---- prefetch next x chunk into the other buffer (readers are 4 steps out)
        if ((t & (TCH - 1)) == 0 && (t + TCH) < T_) {
            const int tb = t + TCH;
            float* sxn = sxg + ((tb >> 2) & 1) * SX_BUF;
            for (int i = j; i < NBT * TCH * I_; i += 64) {
                const int bl = i & 7;
                const int r  = i >> 3;
                const int bp = bl >> 1, e = bl & 1;
                sxn[bp * (TCH * I_ * 2) + r * 2 + e]
                    = x[(size_t)(b0 + bl) * (T_ * I_) + tb * I_ + r];
            }
        }
        barg(g);        // bargA: h1(t) visible; h2(t-1) stores visible; layer0 reads done

        // ================= layer 1 =================
#pragma unroll
        for (int bp = 0; bp < BP; ++bp) { ai[bp]=bi1; af[bp]=bf1; ag[bp]=bg1; ao[bp]=bo1; }
#pragma unroll 4
        for (int k = 0; k < H_; ++k) {
            const float4 wx = sW1x[k * H_ + j];
            const float4 wh = sW1h[k * H_ + j];
            const ull xi = dup2(wx.x), xf = dup2(wx.y), xg = dup2(wx.z), xo = dup2(wx.w);
            const ull hi = dup2(wh.x), hf = dup2(wh.y), hg = dup2(wh.z), ho = dup2(wh.w);
#pragma unroll
            for (int bp = 0; bp < BP; ++bp) {
                const ull xv = *reinterpret_cast<const ull*>(h1w + bp * 128 + k * 2);
                const ull hv = *reinterpret_cast<const ull*>(h2  + bp * 128 + k * 2);
                fma2(ai[bp], xi, xv); fma2(af[bp], xf, xv);
                fma2(ag[bp], xg, xv); fma2(ao[bp], xo, xv);
                fma2(ai[bp], hi, hv); fma2(af[bp], hf, hv);
                fma2(ag[bp], hg, hv); fma2(ao[bp], ho, hv);
            }
        }
        float h2v[NBT];
#pragma unroll
        for (int bp = 0; bp < BP; ++bp) {
            float i0,i1,f0,f1,g0,g1,o0,o1;
            unpk(i0,i1,ai[bp]); unpk(f0,f1,af[bp]); unpk(g0,g1,ag[bp]); unpk(o0,o1,ao[bp]);
            const float cA = sigm(f0)*c2[2*bp]   + sigm(i0)*tanh_f(g0);
            const float cB = sigm(f1)*c2[2*bp+1] + sigm(i1)*tanh_f(g1);
            c2[2*bp]   = cA; h2v[2*bp]   = sigm(o0)*tanh_f(cA);
            c2[2*bp+1] = cB; h2v[2*bp+1] = sigm(o1)*tanh_f(cB);
        }
        barg(g);        // bargB: all reads of h2(t-1) done
#pragma unroll
        for (int bp = 0; bp < BP; ++bp)
            *reinterpret_cast<float2*>(h2 + bp * 128 + j * 2) = make_float2(h2v[2*bp], h2v[2*bp+1]);
        // no end-of-step barrier: next consumer of h2 is layer1(t+1), past bargA(t+1)
    }
    barg(g);            // h2(T-1) visible for FC

    // ---- FC on h2(T-1) ----
    for (int i = j; i < NBT * O_; i += 64) {
        const int bl = i / O_;
        const int o  = i - bl * O_;
        const int bp = bl >> 1, e = bl & 1;
        const float* wrow = Wfc + o * H_;
        float acc = bfc[o];
#pragma unroll 8
        for (int k = 0; k < H_; ++k)
            acc += h2[bp * 128 + k * 2 + e] * wrow[k];
        out[(size_t)(b0 + bl) * O_ + o] = acc;
    }
}

// ---------------------------------------------------------------------------
extern "C" void kernel_launch(void* const* d_in, const int* in_sizes, int n_in,
                              void* d_out, int out_size)
{
    (void)in_sizes; (void)n_in; (void)out_size;
    const float* x    = (const float*)d_in[0];
    const float* Wih0 = (const float*)d_in[1];
    const float* Whh0 = (const float*)d_in[2];
    const float* bih0 = (const float*)d_in[3];
    const float* bhh0 = (const float*)d_in[4];
    const float* Wih1 = (const float*)d_in[5];
    const float* Whh1 = (const float*)d_in[6];
    const float* bih1 = (const float*)d_in[7];
    const float* bhh1 = (const float*)d_in[8];
    const float* Wfc  = (const float*)d_in[9];
    const float* bfc  = (const float*)d_in[10];
    float* out = (float*)d_out;

    cudaFuncSetAttribute(lstm_kernel, cudaFuncAttributeMaxDynamicSharedMemorySize,
                         SM_BYTES);

    prep_kernel<<<32, 256>>>(Wih0, Whh0, bih0, bhh0, Wih1, Whh1, bih1, bhh1);
    lstm_kernel<<<B_ / (GROUPS * NBT), THREADS, SM_BYTES>>>(x, Wfc, bfc, out);
}